// round 15
// baseline (speedup 1.0000x reference)
#include <cuda_runtime.h>
#include <math.h>

// Problem constants (fixed by reference setup_inputs)
#define B 32
#define C 256
#define SPATIAL 4096
#define NCHUNK 32
#define ROWS_PER_CHUNK 128                  // SPATIAL / NCHUNK
#define X_ELEMS (B * SPATIAL * C)           // 33554432
#define BN_EPS 1e-3f

// C-side geometry: 128 C-blocks per batch, 2048 float4 per block
#define CBLK_PER_BATCH 128
#define C_PER_BLK 2048
#define LAG 4
#define NA (B * NCHUNK)                     // 1024 A blocks
#define NC (B * CBLK_PER_BATCH)             // 4096 C blocks
#define NGRID (NA + NC)                     // 5120

// Device state
__device__ float g_psum[B][NCHUNK][C];
__device__ float g_pmax[B][NCHUNK][C];
__device__ float g_gate[B][C];
__device__ unsigned int g_done[B];
__device__ unsigned int g_flag[B];

__global__ void reset_kernel()
{
    const int t = threadIdx.x;
    if (t < B) { g_done[t] = 0u; g_flag[t] = 0u; }
}

// bid -> (type 0=A,1=C ; batch b ; idx = chunk or cblk)
// order: A(b=0..3) | for g in 0..27: [A(4+g), C(g)] | C(28..31)
__device__ __forceinline__ void decode(int bid, int& type, int& b, int& idx)
{
    const int P0 = NCHUNK * LAG;            // 128
    if (bid < P0) { type = 0; b = bid >> 5; idx = bid & 31; return; }
    int j = bid - P0;
    const int GROUPS = B - LAG;             // 28
    const int GSZ = NCHUNK + CBLK_PER_BATCH;// 160
    if (j < GROUPS * GSZ) {
        const int g = j / GSZ, r = j - g * GSZ;
        if (r < NCHUNK) { type = 0; b = LAG + g; idx = r; }
        else            { type = 1; b = g;       idx = r - NCHUNK; }
        return;
    }
    const int jj = j - GROUPS * GSZ;
    type = 1; b = GROUPS + (jj >> 7); idx = jj & 127;
}

__global__ __launch_bounds__(256) void fused_kernel(
    const float* __restrict__ in,
    const float* __restrict__ factor,
    const float* __restrict__ W1,
    const float* __restrict__ b1,
    const float* __restrict__ gamma,
    const float* __restrict__ beta,
    const float* __restrict__ bn_mean,
    const float* __restrict__ bn_var,
    const float* __restrict__ Wg,
    const float* __restrict__ bg,
    const float* __restrict__ gumbel,
    float* __restrict__ out,
    float* __restrict__ gate_out)
{
    const int tid = threadIdx.x;
    int type, b, idx;
    decode((int)blockIdx.x, type, b, idx);

    if (type == 0) {
        // ---------------- A: pool partial (batch b, chunk idx) --------------
        __shared__ float4 sh_s[256];
        __shared__ float4 sh_m[256];
        __shared__ float  pool_s[C];
        __shared__ int    sh_last;

        const int c4 = (tid & 63) << 2;
        const int rg = tid >> 6;
        const float4* p = reinterpret_cast<const float4*>(
            in + ((size_t)(b * SPATIAL + idx * ROWS_PER_CHUNK + rg)) * C + c4);

        float4 s = make_float4(0.f, 0.f, 0.f, 0.f);
        float4 m = make_float4(-INFINITY, -INFINITY, -INFINITY, -INFINITY);
#pragma unroll
        for (int i = 0; i < ROWS_PER_CHUNK / 4; ++i) {
            const float4 v = p[(size_t)i * C];
            s.x += v.x; s.y += v.y; s.z += v.z; s.w += v.w;
            m.x = fmaxf(m.x, v.x); m.y = fmaxf(m.y, v.y);
            m.z = fmaxf(m.z, v.z); m.w = fmaxf(m.w, v.w);
        }
        sh_s[tid] = s; sh_m[tid] = m;
        __syncthreads();

        if (tid < 64) {
            float4 S = sh_s[tid];
            float4 M = sh_m[tid];
#pragma unroll
            for (int g = 1; g < 4; ++g) {
                const float4 s2 = sh_s[tid + 64 * g];
                const float4 m2 = sh_m[tid + 64 * g];
                S.x += s2.x; S.y += s2.y; S.z += s2.z; S.w += s2.w;
                M.x = fmaxf(M.x, m2.x); M.y = fmaxf(M.y, m2.y);
                M.z = fmaxf(M.z, m2.z); M.w = fmaxf(M.w, m2.w);
            }
            *reinterpret_cast<float4*>(&g_psum[b][idx][tid << 2]) = S;
            *reinterpret_cast<float4*>(&g_pmax[b][idx][tid << 2]) = M;
            __threadfence();           // order partials before done-count
        }
        __syncthreads();
        if (tid == 0)
            sh_last = (atomicAdd(&g_done[b], 1u) == NCHUNK - 1) ? 1 : 0;
        __syncthreads();

        if (sh_last) {
            __threadfence();           // acquire all other blocks' partials
            // ---- gate compute for batch b (deterministic fixed order) ----
            float s1 = 0.f, m1 = -INFINITY;
#pragma unroll
            for (int k = 0; k < NCHUNK; ++k) {
                s1 += g_psum[b][k][tid];
                m1 = fmaxf(m1, g_pmax[b][k][tid]);
            }
            const float avg = s1 * (1.0f / (float)SPATIAL);
            const float a0 = factor[0], a1 = factor[1];
            const float fm = fmaxf(a0, a1);
            const float e0 = expf(a0 - fm), e1 = expf(a1 - fm);
            const float inv = 1.0f / (e0 + e1);
            pool_s[tid] = avg * (e0 * inv) + m1 * (e1 * inv);
            __syncthreads();

            float acc = 0.f;
#pragma unroll 8
            for (int k = 0; k < C; ++k)
                acc = fmaf(pool_s[k], W1[k * C + tid], acc);
            float h = acc + b1[tid];
            h = gamma[tid] * (h - bn_mean[tid]) *
                    (1.0f / sqrtf(bn_var[tid] + BN_EPS)) + beta[tid];
            h = fmaxf(h, 0.f);

            const float l0 = fmaf(h, Wg[tid * 2 + 0], bg[tid * 2 + 0]);
            const float l1 = fmaf(h, Wg[tid * 2 + 1], bg[tid * 2 + 1]);
            const float z0 = l0 + gumbel[(b * C + tid) * 2 + 0];
            const float z1 = l1 + gumbel[(b * C + tid) * 2 + 1];
            const float zm = fmaxf(z0, z1);
            const float q0 = expf(z0 - zm), q1 = expf(z1 - zm);
            const float y1 = q1 / (q0 + q1);
            const float hard1 = (z1 > z0) ? 1.0f : 0.0f;  // argmax tie -> 0
            const float w = (hard1 - y1) + y1;            // stop_grad ST

            g_gate[b][tid] = w;
            gate_out[b * C + tid] = w;
            __threadfence();
            __syncthreads();
            if (tid == 0) atomicExch(&g_flag[b], 1u);     // release
        }
    } else {
        // ---------------- C: multiply (batch b, block idx) ------------------
        if (tid == 0) {
            while (atomicAdd(&g_flag[b], 0u) == 0u) __nanosleep(100);
            __threadfence();           // acquire gate
        }
        __syncthreads();

        const float4* in4  = reinterpret_cast<const float4*>(in);
        float4*       out4 = reinterpret_cast<float4*>(out);

        const size_t base = ((size_t)b * CBLK_PER_BATCH + idx) * C_PER_BLK;
        const int c4 = (tid & 63) << 2;   // chunk stride 256 f4 = 4 rows
        const float4 g = *reinterpret_cast<const float4*>(&g_gate[b][c4]);

        float4 v[8];
#pragma unroll
        for (int k = 0; k < 8; ++k)
            v[k] = in4[base + (size_t)k * 256 + tid];
#pragma unroll
        for (int k = 0; k < 8; ++k) {
            v[k].x *= g.x; v[k].y *= g.y; v[k].z *= g.z; v[k].w *= g.w;
        }
#pragma unroll
        for (int k = 0; k < 8; ++k)
            __stcs(&out4[base + (size_t)k * 256 + tid], v[k]);
    }
}

extern "C" void kernel_launch(void* const* d_in, const int* in_sizes, int n_in,
                              void* d_out, int out_size)
{
    const float* inputs = (const float*)d_in[0];
    const float* factor = (const float*)d_in[1];
    const float* W1     = (const float*)d_in[2];
    const float* b1     = (const float*)d_in[3];
    const float* gamma  = (const float*)d_in[4];
    const float* beta   = (const float*)d_in[5];
    const float* bnm    = (const float*)d_in[6];
    const float* bnv    = (const float*)d_in[7];
    const float* Wg     = (const float*)d_in[8];
    const float* bg     = (const float*)d_in[9];
    const float* gumbel = (const float*)d_in[10];

    float* out = (float*)d_out;
    float* gate_out = out + X_ELEMS;   // (B, C) broadcast gate after x

    reset_kernel<<<1, 32>>>();
    fused_kernel<<<NGRID, 256>>>(inputs, factor, W1, b1, gamma, beta, bnm, bnv,
                                 Wg, bg, gumbel, out, gate_out);
}